// round 13
// baseline (speedup 1.0000x reference)
#include <cuda_runtime.h>
#include <cuda_bf16.h>

#define TT 512
#define BB 32
#define VV 8000
#define LL 100
#define SS (2*LL+1)   // 201
#define NEGF (-1e30f)
#define LOG2E 1.4426950408889634f
#define LN2   0.6931471805599453f

#define SWARPS 9      // scan warps per sample
#define OWN   24      // owned states per warp (lanes 8..31)
#define MIR    8      // mirror lanes (0..7) = prev warp's top 8 states
#define NPAIRS 255    // 2-step pairs: pair p covers t = 2p+1, 2p+2 (t up to 510)
#define NGRP  127     // groups of 2 pairs; loop covers pairs 0..253, leftover 254

// Scratch (allocation-free rule: __device__ globals)
__device__ float g_lp[TT*BB*SS];                  // log2-domain emissions (27 MB)
__device__ float g_sc[(size_t)NPAIRS*BB*SS*8];    // [pair][b][s][8]: w0..w4,lpn,pad (52 MB)

__device__ __forceinline__ float ex2f(float x) {
    float r; asm("ex2.approx.ftz.f32 %0, %1;" : "=f"(r) : "f"(x)); return r;
}
__device__ __forceinline__ float lg2f(float x) {
    float r; asm("lg2.approx.ftz.f32 %0, %1;" : "=f"(r) : "f"(x)); return r;
}
__device__ __forceinline__ float lse2w(float x, float y) {       // log2 domain
    float m = fmaxf(x, y);
    return m + lg2f(ex2f(x - m) + ex2f(y - m));
}
__device__ __forceinline__ float lse3w(float x, float y, float z) {
    float m = fmaxf(x, fmaxf(y, z));
    return m + lg2f(ex2f(x - m) + ex2f(y - m) + ex2f(z - m));
}

// ---------------------------------------------------------------------------
// K1a: logZ2 = lg2(sum exp2(x*log2e)) over V (no max pass: inputs bounded),
//      then gather lp_ext (log2 domain). One block per (t,b) row.
// ---------------------------------------------------------------------------
__global__ __launch_bounds__(256) void logz_gather_kernel(const float* __restrict__ acts,
                                                          const int* __restrict__ targets,
                                                          float* __restrict__ out) {
    const int row = blockIdx.x;                    // t*BB + b
    const int b   = row % BB;
    const float* __restrict__ rowp = acts + (size_t)row * VV;
    const float4* __restrict__ p = (const float4*)rowp;
    const int tid = threadIdx.x;

    if (row == 0 && tid == 0) out[0] = 0.f;        // zero the batch-mean accumulator

    float s = 0.f;
    #pragma unroll 4
    for (int i = tid; i < VV/4; i += 256) {
        float4 v = p[i];
        s += ex2f(v.x * LOG2E) + ex2f(v.y * LOG2E)
           + ex2f(v.z * LOG2E) + ex2f(v.w * LOG2E);
    }
    #pragma unroll
    for (int off = 16; off; off >>= 1)
        s += __shfl_xor_sync(0xffffffffu, s, off);

    __shared__ float sv[8];
    __shared__ float sLogZ2;
    int w = tid >> 5;
    if ((tid & 31) == 0) sv[w] = s;
    __syncthreads();
    if (tid == 0) {
        float Sv = sv[0];
        #pragma unroll
        for (int i = 1; i < 8; i++) Sv += sv[i];
        sLogZ2 = lg2f(Sv);                         // logZ in log2 domain
    }
    __syncthreads();

    // Gather 201 extended-label emissions (L1 hits), log2 domain.
    if (tid < SS) {
        int lab = (tid & 1) ? __ldg(&targets[b*LL + (tid >> 1)]) : 0;
        g_lp[(size_t)row * SS + tid] = fmaf(rowp[lab], LOG2E, -sLogZ2);
    }
}

// ---------------------------------------------------------------------------
// K1b: 2-step composed weights, packed [pair][b][s][8]. One block per PAIR,
//      looping all 32 b -> coalesced streaming; output stays L2-resident.
// ---------------------------------------------------------------------------
__global__ __launch_bounds__(256) void weights_kernel(const int* __restrict__ targets) {
    const int pr = blockIdx.x;                 // pair 0..254, t = 2*pr+1
    const int t  = 2*pr + 1;
    const int tid = threadIdx.x;

    __shared__ float slp[SS];

    for (int b = 0; b < BB; b++) {
        if (tid < SS)
            slp[tid] = g_lp[(size_t)(t*BB + b)*SS + tid];
        __syncthreads();
        if (tid < SS) {
            // can_skip flags for s, s-1, s-2
            bool c0 = false, c1 = false, c2 = false;
            {
                int lab0 = (tid & 1) ? __ldg(&targets[b*LL + (tid >> 1)]) : 0;
                if (tid & 1) {
                    int pl = (tid >= 3) ? __ldg(&targets[b*LL + ((tid - 2) >> 1)]) : -1;
                    c0 = (lab0 != 0) && (lab0 != pl);
                }
                if ((tid >= 1) && ((tid - 1) & 1)) {
                    int la = __ldg(&targets[b*LL + ((tid - 1) >> 1)]);
                    int pl = (tid - 1 >= 3) ? __ldg(&targets[b*LL + ((tid - 3) >> 1)]) : -1;
                    c1 = (la != 0) && (la != pl);
                }
                if ((tid >= 2) && ((tid - 2) & 1)) {
                    int la = __ldg(&targets[b*LL + ((tid - 2) >> 1)]);
                    int pl = (tid - 2 >= 3) ? __ldg(&targets[b*LL + ((tid - 4) >> 1)]) : -1;
                    c2 = (la != 0) && (la != pl);
                }
            }
            float L0 = slp[tid];
            float L1 = (tid >= 1) ? slp[tid-1] : NEGF;
            float L2 = (tid >= 2) ? slp[tid-2] : NEGF;
            float4 u0, u1;
            u0.x = L0;                                        // w0
            u0.y = lse2w(L0, L1);                             // w1
            u0.z = lse3w(c0 ? L0 : NEGF, L1, c0 ? L2 : NEGF); // w2
            u0.w = lse2w(c1 ? L1 : NEGF, c0 ? L2 : NEGF);     // w3
            u1.x = (c0 && c2) ? L2 : NEGF;                    // w4
            u1.y = g_lp[(size_t)((t+1)*BB + b)*SS + tid];     // lp_next
            u1.z = 0.f; u1.w = 0.f;
            size_t o = ((size_t)(pr*BB + b)*SS + tid) * 8;
            *(float4*)&g_sc[o]     = u0;
            *(float4*)&g_sc[o + 4] = u1;
        }
        __syncthreads();
    }
}

// ---------------------------------------------------------------------------
// K2: composed 2-step scan, deep pipeline, vectorized L2-resident loads.
// ---------------------------------------------------------------------------

// load group g (pairs 2g, 2g+1): 2x2 LDG.128; g-bound is block-uniform.
#define LOADGRP(g, W) do {                                                     \
    int _g = (g);                                                              \
    if (_g < NGRP) {                                                           \
        size_t _o0 = ((size_t)((2*_g)*BB + b)*SS + sc) * 8;                    \
        size_t _o1 = ((size_t)((2*_g+1)*BB + b)*SS + sc) * 8;                  \
        float4 _u0 = *(const float4*)&g_sc[_o0];                               \
        float4 _u1 = *(const float4*)&g_sc[_o0 + 4];                           \
        float4 _v0 = *(const float4*)&g_sc[_o1];                               \
        float4 _v1 = *(const float4*)&g_sc[_o1 + 4];                           \
        (W)[0]=_u0.x; (W)[1]=_u0.y; (W)[2]=_u0.z; (W)[3]=_u0.w;                \
        (W)[4]=_u1.x; (W)[5]=_u1.y;                                            \
        (W)[6]=_v0.x; (W)[7]=_v0.y; (W)[8]=_v0.z; (W)[9]=_v0.w;                \
        (W)[10]=_v1.x; (W)[11]=_v1.y;                                          \
    } else {                                                                   \
        (W)[0]=(W)[1]=(W)[2]=(W)[3]=(W)[4]=NEGF; (W)[5]=0.f;                   \
        (W)[6]=(W)[7]=(W)[8]=(W)[9]=(W)[10]=NEGF; (W)[11]=0.f;                 \
    }                                                                          \
} while (0)

#define PROCGRP(W, PP) do {                                                    \
    a = pairstep(a, (W)[0], (W)[1], (W)[2], (W)[3], (W)[4], (W)[5]);           \
    a = pairstep(a, (W)[6], (W)[7], (W)[8], (W)[9], (W)[10], (W)[11]);         \
    if (l >= 32 - MIR) bnd[PP][w*MIR + (l - (32 - MIR))] = a;                  \
    __syncthreads();                                                           \
    if (l < MIR) a = (w > 0) ? bnd[PP][(w - 1)*MIR + l] : NEGF;                \
} while (0)

__global__ __launch_bounds__(32*SWARPS) void scan_kernel(const int* __restrict__ targets,
                                                         const int* __restrict__ act_lens,
                                                         const int* __restrict__ label_lens,
                                                         float* __restrict__ out) {
    const int b   = blockIdx.x;
    const int tid = threadIdx.x;
    const int w   = tid >> 5;
    const int l   = tid & 31;
    const int s   = OWN * w + l - MIR;         // state id (mirrors for l<8)
    const bool live = (s >= 0 && s < SS);
    const bool owned = (l >= MIR) && live;
    const int sc  = live ? s : 0;              // clamped (safe addr; dead lanes masked)
    const int alen = act_lens[b];

    __shared__ float bnd[2][SWARPS*MIR];
    __shared__ float fin[SS];

    bool cs = false;                           // can_skip (odd states only)
    if (live && (s & 1)) {
        int cl = targets[b*LL + (s >> 1)];
        int pl = (s >= 3) ? targets[b*LL + ((s - 2) >> 1)] : -1;
        cs = (cl != 0) && (cl != pl);
    }

    auto pairstep = [&](float av, float w0, float w1, float w2, float w3,
                        float w4, float lpn) -> float {
        float x0 = av + w0;
        float x1 = __shfl_up_sync(0xffffffffu, av, 1) + w1;
        float x2 = __shfl_up_sync(0xffffffffu, av, 2) + w2;
        float x3 = __shfl_up_sync(0xffffffffu, av, 3) + w3;
        float x4 = __shfl_up_sync(0xffffffffu, av, 4) + w4;
        float mm = fmaxf(fmaxf(fmaxf(x0, x1), fmaxf(x2, x3)), x4);
        float r = ex2f(x0 - mm) + ex2f(x1 - mm) + ex2f(x2 - mm)
                + ex2f(x3 - mm) + ex2f(x4 - mm);
        float nv = mm + lg2f(r) + lpn;
        return live ? nv : NEGF;
    };
    auto step1 = [&](float av, float lp, int t) -> float {
        float x2 = __shfl_up_sync(0xffffffffu, av, 1);
        float x3 = __shfl_up_sync(0xffffffffu, av, 2);
        float x3e = cs ? x3 : NEGF;
        float mm = fmaxf(av, fmaxf(x2, x3e));
        float r = ex2f(av - mm) + ex2f(x2 - mm) + ex2f(x3e - mm);
        float nv = mm + lg2f(r) + lp;
        nv = (t < alen) ? nv : av;
        return live ? nv : NEGF;
    };

    // alpha[0]
    float a = NEGF;
    if (live && s <= 1) a = g_lp[(size_t)b * SS + s];

    if (alen >= TT) {
        // tail prefetch: leftover pair p=254 (t=509,510) + final step t=511
        float wt[6], lnTail;
        {
            size_t o = ((size_t)(254*BB + b)*SS + sc) * 8;
            float4 u0 = *(const float4*)&g_sc[o];
            float4 u1 = *(const float4*)&g_sc[o + 4];
            wt[0]=u0.x; wt[1]=u0.y; wt[2]=u0.z; wt[3]=u0.w; wt[4]=u1.x; wt[5]=u1.y;
            lnTail = live ? g_lp[(size_t)(511*BB + b)*SS + s] : 0.f;
        }

        // 2-group software pipeline (distance 2)
        float P0[12], P1[12], T0[12], T1[12];
        LOADGRP(0, P0);
        LOADGRP(1, P1);
        __syncthreads();

        for (int g0 = 0; g0 < NGRP - 1; g0 += 2) {      // 126 groups in the loop
            LOADGRP(g0 + 2, T0);
            LOADGRP(g0 + 3, T1);

            PROCGRP(P0, 0);
            PROCGRP(P1, 1);

            #pragma unroll
            for (int i = 0; i < 12; i++) { P0[i] = T0[i]; P1[i] = T1[i]; }
        }
        // last group (126) in P0
        PROCGRP(P0, 0);

        // leftover pair p=254 (t=509,510): consumes mirror lanes 0..3
        a = pairstep(a, wt[0], wt[1], wt[2], wt[3], wt[4], wt[5]);
        // final step t=511: consumes 2 more mirror lanes
        a = step1(a, lnTail, 511);
    } else {
        // fallback: generic per-step smem scan over full g_lp
        __shared__ float sal[2][SS];
        if (live) sal[0][s] = a;
        __syncthreads();
        int cur = 1;
        for (int t = 1; t < TT; t++) {
            if (live) {
                float a1 = sal[cur^1][s];
                float a2 = (s >= 1) ? sal[cur^1][s-1] : NEGF;
                float a3 = (cs && s >= 2) ? sal[cur^1][s-2] : NEGF;
                float mm = fmaxf(a1, fmaxf(a2, a3));
                float r = ex2f(a1 - mm) + ex2f(a2 - mm) + ex2f(a3 - mm);
                float lp = g_lp[(size_t)(t*BB + b)*SS + s];
                float nv = mm + lg2f(r) + lp;
                sal[cur][s] = (t < alen) ? nv : a1;
            }
            __syncthreads();
            cur ^= 1;
        }
        a = live ? sal[cur^1][s] : NEGF;
    }

    if (owned) fin[s] = a;
    __syncthreads();
    if (tid == 0) {
        int sl = 2 * label_lens[b];
        float x = fin[sl], y = fin[sl - 1];
        float m = fmaxf(x, y);
        float ll2 = m + lg2f(ex2f(x - m) + ex2f(y - m));   // log2 domain
        atomicAdd(out, -ll2 * (LN2 / (float)BB));
    }
}

// ---------------------------------------------------------------------------
extern "C" void kernel_launch(void* const* d_in, const int* in_sizes, int n_in,
                              void* d_out, int out_size) {
    const float* acts       = (const float*)d_in[0];
    const int*   targets    = (const int*)d_in[1];
    const int*   act_lens   = (const int*)d_in[2];
    const int*   label_lens = (const int*)d_in[3];
    float* out = (float*)d_out;

    logz_gather_kernel<<<TT*BB, 256>>>(acts, targets, out);
    weights_kernel<<<NPAIRS, 256>>>(targets);
    scan_kernel<<<BB, 32*SWARPS>>>(targets, act_lens, label_lens, out);
}

// round 14
// speedup vs baseline: 1.3356x; 1.3356x over previous
#include <cuda_runtime.h>
#include <cuda_bf16.h>

#define TT 512
#define BB 32
#define VV 8000
#define LL 100
#define SS (2*LL+1)   // 201
#define NEGF (-1e30f)
#define LOG2E 1.4426950408889634f
#define LN2   0.6931471805599453f

#define SWARPS 9      // scan warps per sample
#define OWN   24      // owned states per warp (lanes 8..31)
#define MIR    8      // mirror lanes (0..7) = prev warp's top 8 states
#define NPAIRS 255    // 2-step pairs: pair p covers t = 2p+1, 2p+2 (t up to 510)
#define NGRP  127     // groups of 2 pairs; loop covers pairs 0..253, leftover 254

// Scratch (allocation-free rule: __device__ globals)
__device__ float  g_lp[TT*BB*SS];                 // log2-domain emissions (27 MB)
__device__ float4 g_w4[(size_t)NPAIRS*BB*SS];     // w0..w3 per (pair,b,s)   (26 MB)
__device__ float2 g_w2[(size_t)NPAIRS*BB*SS];     // w4, lp_next             (13 MB)

__device__ __forceinline__ float ex2f(float x) {
    float r; asm("ex2.approx.ftz.f32 %0, %1;" : "=f"(r) : "f"(x)); return r;
}
__device__ __forceinline__ float lg2f(float x) {
    float r; asm("lg2.approx.ftz.f32 %0, %1;" : "=f"(r) : "f"(x)); return r;
}
__device__ __forceinline__ float lse2w(float x, float y) {       // log2 domain
    float m = fmaxf(x, y);
    return m + lg2f(ex2f(x - m) + ex2f(y - m));
}
__device__ __forceinline__ float lse3w(float x, float y, float z) {
    float m = fmaxf(x, fmaxf(y, z));
    return m + lg2f(ex2f(x - m) + ex2f(y - m) + ex2f(z - m));
}

// ---------------------------------------------------------------------------
// K1a: logZ2 = lg2(sum exp2(x*log2e)) over V, then gather lp_ext (log2).
//      One block per (t,b) row.
// ---------------------------------------------------------------------------
__global__ __launch_bounds__(256) void logz_gather_kernel(const float* __restrict__ acts,
                                                          const int* __restrict__ targets,
                                                          float* __restrict__ out) {
    const int row = blockIdx.x;                    // t*BB + b
    const int b   = row % BB;
    const float* __restrict__ rowp = acts + (size_t)row * VV;
    const float4* __restrict__ p = (const float4*)rowp;
    const int tid = threadIdx.x;

    if (row == 0 && tid == 0) out[0] = 0.f;        // zero the batch-mean accumulator

    float s = 0.f;
    #pragma unroll 4
    for (int i = tid; i < VV/4; i += 256) {
        float4 v = p[i];
        s += ex2f(v.x * LOG2E) + ex2f(v.y * LOG2E)
           + ex2f(v.z * LOG2E) + ex2f(v.w * LOG2E);
    }
    #pragma unroll
    for (int off = 16; off; off >>= 1)
        s += __shfl_xor_sync(0xffffffffu, s, off);

    __shared__ float sv[8];
    __shared__ float sLogZ2;
    int w = tid >> 5;
    if ((tid & 31) == 0) sv[w] = s;
    __syncthreads();
    if (tid == 0) {
        float Sv = sv[0];
        #pragma unroll
        for (int i = 1; i < 8; i++) Sv += sv[i];
        sLogZ2 = lg2f(Sv);                         // logZ in log2 domain
    }
    __syncthreads();

    if (tid < SS) {
        int lab = (tid & 1) ? __ldg(&targets[b*LL + (tid >> 1)]) : 0;
        g_lp[(size_t)row * SS + tid] = fmaf(rowp[lab], LOG2E, -sLogZ2);
    }
}

// ---------------------------------------------------------------------------
// K1b: 2-step composed weights. One block per (pair, b) -> 8160 parallel
//      blocks, coalesced dense float4/float2 stores. Output stays L2-resident.
// ---------------------------------------------------------------------------
__global__ __launch_bounds__(256) void weights_kernel(const int* __restrict__ targets) {
    const int pr = blockIdx.x / BB;            // pair 0..254, t = 2*pr+1
    const int b  = blockIdx.x % BB;
    const int t  = 2*pr + 1;
    const int tid = threadIdx.x;

    __shared__ float slp[SS];
    __shared__ unsigned char scs[SS];

    if (tid < SS) {
        slp[tid] = g_lp[(size_t)(t*BB + b)*SS + tid];
        bool csf = false;
        if (tid & 1) {
            int lab = __ldg(&targets[b*LL + (tid >> 1)]);
            int pl  = (tid >= 3) ? __ldg(&targets[b*LL + ((tid - 2) >> 1)]) : -1;
            csf = (lab != 0) && (lab != pl);
        }
        scs[tid] = csf ? 1 : 0;
    }
    __syncthreads();

    if (tid < SS) {
        float L0 = slp[tid];
        float L1 = (tid >= 1) ? slp[tid-1] : NEGF;
        float L2 = (tid >= 2) ? slp[tid-2] : NEGF;
        bool c0 = scs[tid];
        bool c1 = (tid >= 1) ? (scs[tid-1] != 0) : false;
        bool c2 = (tid >= 2) ? (scs[tid-2] != 0) : false;
        float4 u;
        u.x = L0;                                        // w0
        u.y = lse2w(L0, L1);                             // w1
        u.z = lse3w(c0 ? L0 : NEGF, L1, c0 ? L2 : NEGF); // w2
        u.w = lse2w(c1 ? L1 : NEGF, c0 ? L2 : NEGF);     // w3
        float2 v;
        v.x = (c0 && c2) ? L2 : NEGF;                    // w4
        v.y = g_lp[(size_t)((t+1)*BB + b)*SS + tid];     // lp_next
        size_t o = (size_t)(pr*BB + b)*SS + tid;
        g_w4[o] = u;
        g_w2[o] = v;
    }
}

// ---------------------------------------------------------------------------
// K2: composed 2-step scan, deep pipeline, dense vectorized L2-resident loads.
// ---------------------------------------------------------------------------

// load group g (pairs 2g, 2g+1): per pair 1 LDG.128 + 1 LDG.64 (dense stride)
#define LOADGRP(g, W) do {                                                     \
    int _g = (g);                                                              \
    if (_g < NGRP) {                                                           \
        size_t _i0 = (size_t)((2*_g)*BB + b)*SS + sc;                          \
        size_t _i1 = (size_t)((2*_g+1)*BB + b)*SS + sc;                        \
        float4 _u = g_w4[_i0]; float2 _v = g_w2[_i0];                          \
        float4 _x = g_w4[_i1]; float2 _y = g_w2[_i1];                          \
        (W)[0]=_u.x; (W)[1]=_u.y; (W)[2]=_u.z; (W)[3]=_u.w;                    \
        (W)[4]=_v.x; (W)[5]=_v.y;                                              \
        (W)[6]=_x.x; (W)[7]=_x.y; (W)[8]=_x.z; (W)[9]=_x.w;                    \
        (W)[10]=_y.x; (W)[11]=_y.y;                                            \
    } else {                                                                   \
        (W)[0]=(W)[1]=(W)[2]=(W)[3]=(W)[4]=NEGF; (W)[5]=0.f;                   \
        (W)[6]=(W)[7]=(W)[8]=(W)[9]=(W)[10]=NEGF; (W)[11]=0.f;                 \
    }                                                                          \
} while (0)

#define PROCGRP(W, PP) do {                                                    \
    a = pairstep(a, (W)[0], (W)[1], (W)[2], (W)[3], (W)[4], (W)[5]);           \
    a = pairstep(a, (W)[6], (W)[7], (W)[8], (W)[9], (W)[10], (W)[11]);         \
    if (l >= 32 - MIR) bnd[PP][w*MIR + (l - (32 - MIR))] = a;                  \
    __syncthreads();                                                           \
    if (l < MIR) a = (w > 0) ? bnd[PP][(w - 1)*MIR + l] : NEGF;                \
} while (0)

__global__ __launch_bounds__(32*SWARPS) void scan_kernel(const int* __restrict__ targets,
                                                         const int* __restrict__ act_lens,
                                                         const int* __restrict__ label_lens,
                                                         float* __restrict__ out) {
    const int b   = blockIdx.x;
    const int tid = threadIdx.x;
    const int w   = tid >> 5;
    const int l   = tid & 31;
    const int s   = OWN * w + l - MIR;         // state id (mirrors for l<8)
    const bool live = (s >= 0 && s < SS);
    const bool owned = (l >= MIR) && live;
    const int sc  = live ? s : 0;              // clamped (safe addr; dead lanes masked)
    const int alen = act_lens[b];

    __shared__ float bnd[2][SWARPS*MIR];
    __shared__ float fin[SS];

    bool cs = false;                           // can_skip (odd states only)
    if (live && (s & 1)) {
        int cl = targets[b*LL + (s >> 1)];
        int pl = (s >= 3) ? targets[b*LL + ((s - 2) >> 1)] : -1;
        cs = (cl != 0) && (cl != pl);
    }

    auto pairstep = [&](float av, float w0, float w1, float w2, float w3,
                        float w4, float lpn) -> float {
        float x0 = av + w0;
        float x1 = __shfl_up_sync(0xffffffffu, av, 1) + w1;
        float x2 = __shfl_up_sync(0xffffffffu, av, 2) + w2;
        float x3 = __shfl_up_sync(0xffffffffu, av, 3) + w3;
        float x4 = __shfl_up_sync(0xffffffffu, av, 4) + w4;
        float mm = fmaxf(fmaxf(fmaxf(x0, x1), fmaxf(x2, x3)), x4);
        float r = ex2f(x0 - mm) + ex2f(x1 - mm) + ex2f(x2 - mm)
                + ex2f(x3 - mm) + ex2f(x4 - mm);
        float nv = mm + lg2f(r) + lpn;
        return live ? nv : NEGF;
    };
    auto step1 = [&](float av, float lp, int t) -> float {
        float x2 = __shfl_up_sync(0xffffffffu, av, 1);
        float x3 = __shfl_up_sync(0xffffffffu, av, 2);
        float x3e = cs ? x3 : NEGF;
        float mm = fmaxf(av, fmaxf(x2, x3e));
        float r = ex2f(av - mm) + ex2f(x2 - mm) + ex2f(x3e - mm);
        float nv = mm + lg2f(r) + lp;
        nv = (t < alen) ? nv : av;
        return live ? nv : NEGF;
    };

    // alpha[0]
    float a = NEGF;
    if (live && s <= 1) a = g_lp[(size_t)b * SS + s];

    if (alen >= TT) {
        // tail prefetch: leftover pair p=254 (t=509,510) + final step t=511
        float wt[6], lnTail;
        {
            size_t i0 = (size_t)(254*BB + b)*SS + sc;
            float4 u = g_w4[i0]; float2 v = g_w2[i0];
            wt[0]=u.x; wt[1]=u.y; wt[2]=u.z; wt[3]=u.w; wt[4]=v.x; wt[5]=v.y;
            lnTail = live ? g_lp[(size_t)(511*BB + b)*SS + s] : 0.f;
        }

        // 2-group software pipeline (distance 2)
        float P0[12], P1[12], T0[12], T1[12];
        LOADGRP(0, P0);
        LOADGRP(1, P1);
        __syncthreads();

        for (int g0 = 0; g0 < NGRP - 1; g0 += 2) {      // 126 groups in the loop
            LOADGRP(g0 + 2, T0);
            LOADGRP(g0 + 3, T1);

            PROCGRP(P0, 0);
            PROCGRP(P1, 1);

            #pragma unroll
            for (int i = 0; i < 12; i++) { P0[i] = T0[i]; P1[i] = T1[i]; }
        }
        // last group (126) in P0
        PROCGRP(P0, 0);

        // leftover pair p=254 (t=509,510): consumes mirror lanes 0..3
        a = pairstep(a, wt[0], wt[1], wt[2], wt[3], wt[4], wt[5]);
        // final step t=511: consumes 2 more mirror lanes
        a = step1(a, lnTail, 511);
    } else {
        // fallback: generic per-step smem scan over full g_lp
        __shared__ float sal[2][SS];
        if (live) sal[0][s] = a;
        __syncthreads();
        int cur = 1;
        for (int t = 1; t < TT; t++) {
            if (live) {
                float a1 = sal[cur^1][s];
                float a2 = (s >= 1) ? sal[cur^1][s-1] : NEGF;
                float a3 = (cs && s >= 2) ? sal[cur^1][s-2] : NEGF;
                float mm = fmaxf(a1, fmaxf(a2, a3));
                float r = ex2f(a1 - mm) + ex2f(a2 - mm) + ex2f(a3 - mm);
                float lp = g_lp[(size_t)(t*BB + b)*SS + s];
                float nv = mm + lg2f(r) + lp;
                sal[cur][s] = (t < alen) ? nv : a1;
            }
            __syncthreads();
            cur ^= 1;
        }
        a = live ? sal[cur^1][s] : NEGF;
    }

    if (owned) fin[s] = a;
    __syncthreads();
    if (tid == 0) {
        int sl = 2 * label_lens[b];
        float x = fin[sl], y = fin[sl - 1];
        float m = fmaxf(x, y);
        float ll2 = m + lg2f(ex2f(x - m) + ex2f(y - m));   // log2 domain
        atomicAdd(out, -ll2 * (LN2 / (float)BB));
    }
}

// ---------------------------------------------------------------------------
extern "C" void kernel_launch(void* const* d_in, const int* in_sizes, int n_in,
                              void* d_out, int out_size) {
    const float* acts       = (const float*)d_in[0];
    const int*   targets    = (const int*)d_in[1];
    const int*   act_lens   = (const int*)d_in[2];
    const int*   label_lens = (const int*)d_in[3];
    float* out = (float*)d_out;

    logz_gather_kernel<<<TT*BB, 256>>>(acts, targets, out);
    weights_kernel<<<NPAIRS*BB, 256>>>(targets);
    scan_kernel<<<BB, 32*SWARPS>>>(targets, act_lens, label_lens, out);
}